// round 14
// baseline (speedup 1.0000x reference)
#include <cuda_runtime.h>
#include <cuda_bf16.h>
#include <cuda_fp16.h>
#include <math.h>
#include <stdint.h>

// Problem constants
#define B_  2
#define S_  2048
#define HID_ 4096
#define NH_ 32
#define NKV_ 8
#define HD_ 128
#define M_TOT (B_ * S_)          // 4096
#define NKVD (NKV_ * HD_)        // 1024
#define NQKV (HID_ + 2 * NKVD)   // 6144 fused QKV output cols

// fp16 scratch
__device__ __half g_A2 [(size_t)M_TOT * HID_];   // hidden fp16
__device__ __half g_W3 [(size_t)NQKV  * HID_];   // fused [Wq;Wk;Wv]
__device__ __half g_Wo2[(size_t)HID_  * HID_];
__device__ __half g_O2 [(size_t)M_TOT * HID_];   // attention output fp16
__device__ __half g_qh [(size_t)M_TOT * NH_  * HD_];  // q (rope in-place)
__device__ __half g_kh [(size_t)M_TOT * NKVD];        // k (rope in-place)
__device__ __half g_vf [(size_t)M_TOT * NKVD];        // v pre-transpose
__device__ __half g_vth[(size_t)M_TOT * NKVD];        // v [b][kvh][d][s]

// ---------------------------------------------------------------------------
struct alignas(8) HF4 { __half v[4]; };

// cvtH: fp32 -> fp16 flat, 16 elements/thread (MLP=4)
__global__ void cvtH_kernel(const float* __restrict__ src,
                            __half* __restrict__ dst, int total16) {
    int i = blockIdx.x * blockDim.x + threadIdx.x;
    if (i >= total16) return;
    float4 x[4];
#pragma unroll
    for (int j = 0; j < 4; j++)
        x[j] = *(const float4*)(src + (size_t)i * 16 + j * 4);
#pragma unroll
    for (int j = 0; j < 4; j++) {
        HF4 H;
        H.v[0] = __float2half_rn(x[j].x);
        H.v[1] = __float2half_rn(x[j].y);
        H.v[2] = __float2half_rn(x[j].z);
        H.v[3] = __float2half_rn(x[j].w);
        *(HF4*)(dst + (size_t)i * 16 + j * 4) = H;
    }
}

// rope16: in-place RoPE on fp16 q/k (q prescaled by qsc)
#define ROPE_TOTAL (B_ * S_ * (NH_ + NKV_) * 64)

__global__ void rope16_kernel(__half* __restrict__ qh,
                              __half* __restrict__ kh,
                              const int* __restrict__ pos_ids, float qsc) {
    int idx = blockIdx.x * blockDim.x + threadIdx.x;
    if (idx >= ROPE_TOTAL) return;
    int d    = idx & 63;
    int rest = idx >> 6;
    int head = rest % (NH_ + NKV_);
    rest    /= (NH_ + NKV_);
    int s = rest % S_;
    int b = rest / S_;

    float inv = powf(10000.0f, -(float)d * (1.0f / 64.0f));
    float ang = (float)pos_ids[s] * inv;
    float c = cosf(ang), sn = sinf(ang);

    __half* base = (head < NH_)
        ? qh + ((size_t)(b * S_ + s) * NH_ + head) * HD_
        : kh + ((size_t)(b * S_ + s) * NKV_ + (head - NH_)) * HD_;
    float sc = (head < NH_) ? qsc : 1.0f;

    float x1 = __half2float(base[d]), x2 = __half2float(base[d + 64]);
    base[d]      = __float2half_rn((x1 * c - x2 * sn) * sc);
    base[d + 64] = __float2half_rn((x2 * c + x1 * sn) * sc);
}

// vt16: fp16 v [b*S+s][kvh][d] -> fp16 [b][kvh][d][s] (pure transpose)
__global__ void vt16_kernel(const __half* __restrict__ v,
                            __half* __restrict__ th) {
    int i = blockIdx.x * blockDim.x + threadIdx.x;
    int s    = i % S_;
    int rest = i / S_;
    int d4   = rest % (HD_ / 4);
    rest    /= (HD_ / 4);
    int kvh  = rest % NKV_;
    int b    = rest / NKV_;
    HF4 x = *(const HF4*)(v + ((size_t)(b * S_ + s) * NKV_ + kvh) * HD_ + d4 * 4);
#pragma unroll
    for (int j = 0; j < 4; j++) {
        size_t o = ((size_t)(b * NKV_ + kvh) * HD_ + d4 * 4 + j) * S_ + s;
        th[o] = x.v[j];
    }
}

// ---------------------------------------------------------------------------
// mma / ldmatrix helpers
// ---------------------------------------------------------------------------
__device__ __forceinline__ void ldsm4(uint32_t* r, uint32_t addr) {
    asm volatile("ldmatrix.sync.aligned.m8n8.x4.shared.b16 {%0,%1,%2,%3}, [%4];\n"
                 : "=r"(r[0]), "=r"(r[1]), "=r"(r[2]), "=r"(r[3]) : "r"(addr));
}
__device__ __forceinline__ void mma_f16(float* c, const uint32_t* a,
                                        uint32_t b0, uint32_t b1) {
    asm volatile("mma.sync.aligned.m16n8k16.row.col.f32.f16.f16.f32 "
                 "{%0,%1,%2,%3}, {%4,%5,%6,%7}, {%8,%9}, {%0,%1,%2,%3};\n"
                 : "+f"(c[0]), "+f"(c[1]), "+f"(c[2]), "+f"(c[3])
                 : "r"(a[0]), "r"(a[1]), "r"(a[2]), "r"(a[3]), "r"(b0), "r"(b1));
}
__device__ __forceinline__ uint32_t cvt_f16x2(float lo, float hi) {
    uint32_t r;
    asm("cvt.rn.f16x2.f32 %0, %1, %2;" : "=r"(r) : "f"(hi), "f"(lo));
    return r;
}

// ---------------------------------------------------------------------------
// fp16 tensor-core GEMM (NT): 128x128x32 tile, 256 threads, warp tile 64x32,
// 3-stage cp.async. Epilogue routes 128-col tiles to (C0,C1,C2);
// half_out selects fp16 vs fp32 output.
// ---------------------------------------------------------------------------
#define HG_BK 32
#define HG_LDS 40
#define HG_STAGE_ELEMS (128 * HG_LDS)
#define HG_STAGE_BYTES (HG_STAGE_ELEMS * 2)

__global__ __launch_bounds__(256, 2) void hgemm_nt(
    const __half* __restrict__ A, const __half* __restrict__ B,
    void* __restrict__ C0, void* __restrict__ C1, void* __restrict__ C2,
    int M, int K, int half_out) {
    __shared__ __half As[3][HG_STAGE_ELEMS];
    __shared__ __half Bs[3][HG_STAGE_ELEMS];

    const int t    = threadIdx.x;
    const int lane = t & 31;
    const int w    = t >> 5;
    const int wm   = w >> 2;
    const int wn   = w & 3;

    const __half* Ab = A + (size_t)blockIdx.y * 128 * K;
    const __half* Bb = B + (size_t)blockIdx.x * 128 * K;

    const uint32_t as0 = (uint32_t)__cvta_generic_to_shared(&As[0][0]);
    const uint32_t bs0 = (uint32_t)__cvta_generic_to_shared(&Bs[0][0]);

    const int ldr = t >> 2;
    const int ldc = (t & 3) * 8;

    auto load_tile = [&](int kt, int st) {
#pragma unroll
        for (int it = 0; it < 2; it++) {
            int r = ldr + it * 64;
            const __half* ga = Ab + (size_t)r * K + kt * HG_BK + ldc;
            uint32_t sa = as0 + st * HG_STAGE_BYTES + (r * HG_LDS + ldc) * 2;
            asm volatile("cp.async.cg.shared.global [%0], [%1], 16;\n" :: "r"(sa), "l"(ga));
            const __half* gb = Bb + (size_t)r * K + kt * HG_BK + ldc;
            uint32_t sb = bs0 + st * HG_STAGE_BYTES + (r * HG_LDS + ldc) * 2;
            asm volatile("cp.async.cg.shared.global [%0], [%1], 16;\n" :: "r"(sb), "l"(gb));
        }
    };

    const int KT = K / HG_BK;
    load_tile(0, 0);
    asm volatile("cp.async.commit_group;\n");
    load_tile(1, 1);
    asm volatile("cp.async.commit_group;\n");

    float acc[4][4][4];
#pragma unroll
    for (int i = 0; i < 4; i++)
#pragma unroll
        for (int j = 0; j < 4; j++)
#pragma unroll
            for (int r = 0; r < 4; r++) acc[i][j][r] = 0.f;

    const int g  = lane >> 3;
    const int lr = lane & 7;
    const int a_row = ((g & 1) << 3) + lr;
    const int a_k   = (g >> 1) << 3;
    const int b_row = ((g >> 1) << 3) + lr;
    const int b_k   = (g & 1) << 3;

    for (int kt = 0; kt < KT; kt++) {
        asm volatile("cp.async.wait_group 1;\n");
        __syncthreads();
        if (kt + 2 < KT) load_tile(kt + 2, (kt + 2) % 3);
        asm volatile("cp.async.commit_group;\n");

        const int st = kt % 3;
        const uint32_t asb = as0 + st * HG_STAGE_BYTES;
        const uint32_t bsb = bs0 + st * HG_STAGE_BYTES;

#pragma unroll
        for (int ks = 0; ks < 2; ks++) {
            uint32_t af[4][4];
            uint32_t bf_[4][2];
#pragma unroll
            for (int mf = 0; mf < 4; mf++) {
                int row = wm * 64 + mf * 16 + a_row;
                ldsm4(af[mf], asb + (row * HG_LDS + ks * 16 + a_k) * 2);
            }
#pragma unroll
            for (int np = 0; np < 2; np++) {
                int row = wn * 32 + np * 16 + b_row;
                uint32_t tmp[4];
                ldsm4(tmp, bsb + (row * HG_LDS + ks * 16 + b_k) * 2);
                bf_[np*2][0] = tmp[0]; bf_[np*2][1] = tmp[1];
                bf_[np*2+1][0] = tmp[2]; bf_[np*2+1][1] = tmp[3];
            }
#pragma unroll
            for (int mf = 0; mf < 4; mf++)
#pragma unroll
                for (int nf = 0; nf < 4; nf++)
                    mma_f16(acc[mf][nf], af[mf], bf_[nf][0], bf_[nf][1]);
        }
    }

    // epilogue with QKV column routing (Q: 4096 cols, K: 1024, V: 1024)
    const int gc0 = blockIdx.x * 128;
    void* Cd; int cstride, cbase;
    if (gc0 < HID_)                { Cd = C0; cstride = NH_ * HD_; cbase = 0; }
    else if (gc0 < HID_ + NKVD)    { Cd = C1; cstride = NKVD;      cbase = HID_; }
    else                           { Cd = C2; cstride = NKVD;      cbase = HID_ + NKVD; }

#pragma unroll
    for (int mf = 0; mf < 4; mf++) {
        int row = blockIdx.y * 128 + wm * 64 + mf * 16 + (lane >> 2);
#pragma unroll
        for (int nf = 0; nf < 4; nf++) {
            int col = gc0 + wn * 32 + nf * 8 + (lane & 3) * 2 - cbase;
            if (half_out) {
                __half* Ch = (__half*)Cd;
                __half2 v0 = __floats2half2_rn(acc[mf][nf][0], acc[mf][nf][1]);
                __half2 v1 = __floats2half2_rn(acc[mf][nf][2], acc[mf][nf][3]);
                *(__half2*)&Ch[(size_t)row * cstride + col]       = v0;
                *(__half2*)&Ch[(size_t)(row + 8) * cstride + col] = v1;
            } else {
                float* Cf = (float*)Cd;
                float2 v0 = {acc[mf][nf][0], acc[mf][nf][1]};
                float2 v1 = {acc[mf][nf][2], acc[mf][nf][3]};
                *(float2*)&Cf[(size_t)row * cstride + col]       = v0;
                *(float2*)&Cf[(size_t)(row + 8) * cstride + col] = v1;
            }
        }
    }
}

// ---------------------------------------------------------------------------
// Tensor-core flash attention, single-term fp16, fp16 output.
// BQ=128, BK=64, HD=128, 256 threads (8 warps x 16 q-rows).
// ---------------------------------------------------------------------------
#define FQ_LDS 136
#define FV_LDS 72
#define F_Q 0
#define F_STAGE0 17408
#define F_STAGE (8704 + 9216)
#define F_K 0
#define F_VT 8704
#define FLASH_SMEM_ELEMS (F_STAGE0 + 2 * F_STAGE)
#define FLASH_SMEM_BYTES (FLASH_SMEM_ELEMS * 2)

__global__ __launch_bounds__(256, 1) void flash_tc(
    const __half* __restrict__ qh, const __half* __restrict__ kh,
    const __half* __restrict__ vth, __half* __restrict__ o) {
    const int qt  = gridDim.x - 1 - blockIdx.x;
    const int h   = blockIdx.y;
    const int b   = blockIdx.z;
    const int kvh = h >> 2;

    extern __shared__ __half fsm[];
    const uint32_t sb = (uint32_t)__cvta_generic_to_shared(fsm);

    const int t    = threadIdx.x;
    const int lane = t & 31;
    const int w    = t >> 5;

    {
        int r = t >> 1;
        const __half* gq = qh + ((size_t)(b * S_ + qt * 128 + r) * NH_ + h) * HD_;
#pragma unroll
        for (int j = 0; j < 8; j++) {
            int col = (t & 1) * 64 + j * 8;
            uint32_t sh = sb + (F_Q + r * FQ_LDS + col) * 2;
            asm volatile("cp.async.cg.shared.global [%0], [%1], 16;\n" :: "r"(sh), "l"(gq + col));
        }
        asm volatile("cp.async.commit_group;\n");
    }

    auto load_kv = [&](int kt, int st) {
        uint32_t stb = sb + (F_STAGE0 + st * F_STAGE) * 2;
        {
            int r  = t >> 2;
            int cb = (t & 3) * 32;
            size_t go = ((size_t)(b * S_ + kt * 64 + r) * NKV_ + kvh) * HD_;
#pragma unroll
            for (int j = 0; j < 4; j++) {
                int col = cb + j * 8;
                asm volatile("cp.async.cg.shared.global [%0], [%1], 16;\n"
                             :: "r"(stb + (F_K + r * FQ_LDS + col) * 2), "l"(kh + go + col));
            }
        }
        {
            int rv = t >> 1;
            int cv = (t & 1) * 32;
            size_t go = ((size_t)(b * NKV_ + kvh) * HD_ + rv) * S_ + kt * 64;
#pragma unroll
            for (int j = 0; j < 4; j++) {
                int col = cv + j * 8;
                asm volatile("cp.async.cg.shared.global [%0], [%1], 16;\n"
                             :: "r"(stb + (F_VT + rv * FV_LDS + col) * 2), "l"(vth + go + col));
            }
        }
    };

    const int ktmax = 2 * qt + 1;
    load_kv(0, 0);
    asm volatile("cp.async.commit_group;\n");
    if (ktmax >= 1) load_kv(1, 1);
    asm volatile("cp.async.commit_group;\n");

    const int g  = lane >> 3;
    const int lr = lane & 7;
    const int a_row = ((g & 1) << 3) + lr;
    const int a_k   = (g >> 1) << 3;
    const int b_row = ((g >> 1) << 3) + lr;
    const int b_k   = (g & 1) << 3;

    float out[16][4];
#pragma unroll
    for (int i = 0; i < 16; i++)
#pragma unroll
        for (int j = 0; j < 4; j++) out[i][j] = 0.f;
    float m0 = -INFINITY, m1 = -INFINITY, l0 = 0.f, l1 = 0.f;

    const int qrow_base = qt * 128 + w * 16;

    for (int kt = 0; kt <= ktmax; kt++) {
        asm volatile("cp.async.wait_group 1;\n");
        __syncthreads();
        const int st = kt & 1;
        const uint32_t stb = sb + (F_STAGE0 + st * F_STAGE) * 2;

        if (kt * 64 <= qrow_base + 15) {
            float accs[8][4];
#pragma unroll
            for (int i = 0; i < 8; i++)
#pragma unroll
                for (int j = 0; j < 4; j++) accs[i][j] = 0.f;

#pragma unroll
            for (int kc = 0; kc < 8; kc++) {
                uint32_t aH[4];
                ldsm4(aH, sb + (F_Q + (w * 16 + a_row) * FQ_LDS + kc * 16 + a_k) * 2);
#pragma unroll
                for (int nf2 = 0; nf2 < 4; nf2++) {
                    uint32_t bh[4];
                    ldsm4(bh, stb + (F_K + (nf2 * 16 + b_row) * FQ_LDS + kc * 16 + b_k) * 2);
                    mma_f16(accs[nf2 * 2],     aH, bh[0], bh[1]);
                    mma_f16(accs[nf2 * 2 + 1], aH, bh[2], bh[3]);
                }
            }

            if (kt * 64 + 63 > qrow_base) {
                int r0 = qrow_base + (lane >> 2);
#pragma unroll
                for (int nf = 0; nf < 8; nf++) {
#pragma unroll
                    for (int e = 0; e < 4; e++) {
                        int col = kt * 64 + nf * 8 + (lane & 3) * 2 + (e & 1);
                        int row = r0 + (e >> 1) * 8;
                        if (col > row) accs[nf][e] = -1.0e30f;
                    }
                }
            }

            float mx0 = -INFINITY, mx1 = -INFINITY;
#pragma unroll
            for (int nf = 0; nf < 8; nf++) {
                mx0 = fmaxf(mx0, fmaxf(accs[nf][0], accs[nf][1]));
                mx1 = fmaxf(mx1, fmaxf(accs[nf][2], accs[nf][3]));
            }
            mx0 = fmaxf(mx0, __shfl_xor_sync(0xffffffffu, mx0, 1));
            mx0 = fmaxf(mx0, __shfl_xor_sync(0xffffffffu, mx0, 2));
            mx1 = fmaxf(mx1, __shfl_xor_sync(0xffffffffu, mx1, 1));
            mx1 = fmaxf(mx1, __shfl_xor_sync(0xffffffffu, mx1, 2));
            float mn0 = fmaxf(m0, mx0), mn1 = fmaxf(m1, mx1);
            float c0 = exp2f(m0 - mn0), c1 = exp2f(m1 - mn1);
            m0 = mn0; m1 = mn1;

            float s0 = 0.f, s1 = 0.f;
#pragma unroll
            for (int nf = 0; nf < 8; nf++) {
                accs[nf][0] = exp2f(accs[nf][0] - mn0);
                accs[nf][1] = exp2f(accs[nf][1] - mn0);
                accs[nf][2] = exp2f(accs[nf][2] - mn1);
                accs[nf][3] = exp2f(accs[nf][3] - mn1);
                s0 += accs[nf][0] + accs[nf][1];
                s1 += accs[nf][2] + accs[nf][3];
            }
            s0 += __shfl_xor_sync(0xffffffffu, s0, 1);
            s0 += __shfl_xor_sync(0xffffffffu, s0, 2);
            s1 += __shfl_xor_sync(0xffffffffu, s1, 1);
            s1 += __shfl_xor_sync(0xffffffffu, s1, 2);
            l0 = l0 * c0 + s0;
            l1 = l1 * c1 + s1;

            uint32_t pH[4][4];
#pragma unroll
            for (int kc2 = 0; kc2 < 4; kc2++) {
#pragma unroll
                for (int q4 = 0; q4 < 4; q4++) {
                    int nf = kc2 * 2 + (q4 >> 1);
                    int e0 = (q4 & 1) * 2;
                    pH[kc2][q4] = cvt_f16x2(accs[nf][e0], accs[nf][e0 + 1]);
                }
            }

#pragma unroll
            for (int i = 0; i < 16; i++) {
                out[i][0] *= c0; out[i][1] *= c0;
                out[i][2] *= c1; out[i][3] *= c1;
            }

#pragma unroll
            for (int kc2 = 0; kc2 < 4; kc2++) {
#pragma unroll
                for (int nd = 0; nd < 8; nd++) {
                    uint32_t bh[4];
                    ldsm4(bh, stb + (F_VT + (nd * 16 + b_row) * FV_LDS + kc2 * 16 + b_k) * 2);
                    mma_f16(out[nd * 2],     pH[kc2], bh[0], bh[1]);
                    mma_f16(out[nd * 2 + 1], pH[kc2], bh[2], bh[3]);
                }
            }
        }

        __syncthreads();
        if (kt + 2 <= ktmax) load_kv(kt + 2, st);
        asm volatile("cp.async.commit_group;\n");
    }

    float inv0 = 1.0f / l0, inv1 = 1.0f / l1;
    int r0 = qt * 128 + w * 16 + (lane >> 2);
#pragma unroll
    for (int nfd = 0; nfd < 16; nfd++) {
        int col = nfd * 8 + (lane & 3) * 2;
        __half2 v0 = __floats2half2_rn(out[nfd][0] * inv0, out[nfd][1] * inv0);
        __half2 v1 = __floats2half2_rn(out[nfd][2] * inv1, out[nfd][3] * inv1);
        *(__half2*)&o[((size_t)(b * S_ + r0) * NH_ + h) * HD_ + col]       = v0;
        *(__half2*)&o[((size_t)(b * S_ + r0 + 8) * NH_ + h) * HD_ + col]   = v1;
    }
}

// ---------------------------------------------------------------------------
// Launch
// ---------------------------------------------------------------------------
extern "C" void kernel_launch(void* const* d_in, const int* in_sizes, int n_in,
                              void* d_out, int out_size) {
    const float* hidden = (const float*)d_in[0];
    const int*   pos    = (const int*)  d_in[2];
    const float* wq     = (const float*)d_in[3];
    const float* wk     = (const float*)d_in[4];
    const float* wv     = (const float*)d_in[5];
    const float* wo     = (const float*)d_in[6];
    float* out = (float*)d_out;

    __half *a2, *w3, *wo2, *o2, *qhp, *khp, *vfp, *vthp;
    cudaGetSymbolAddress((void**)&a2, g_A2);
    cudaGetSymbolAddress((void**)&w3, g_W3);
    cudaGetSymbolAddress((void**)&wo2, g_Wo2);
    cudaGetSymbolAddress((void**)&o2, g_O2);
    cudaGetSymbolAddress((void**)&qhp, g_qh);
    cudaGetSymbolAddress((void**)&khp, g_kh);
    cudaGetSymbolAddress((void**)&vfp, g_vf);
    cudaGetSymbolAddress((void**)&vthp, g_vth);

    const int big16   = (M_TOT * HID_) / 16;
    const int small16 = (NKVD * HID_) / 16;
    cvtH_kernel<<<(big16 + 255) / 256, 256>>>(hidden, a2, big16);
    cvtH_kernel<<<(big16 + 255) / 256, 256>>>(wq, w3, big16);
    cvtH_kernel<<<(small16 + 255) / 256, 256>>>(wk, w3 + (size_t)HID_ * HID_, small16);
    cvtH_kernel<<<(small16 + 255) / 256, 256>>>(wv, w3 + (size_t)(HID_ + NKVD) * HID_, small16);
    cvtH_kernel<<<(big16 + 255) / 256, 256>>>(wo, wo2, big16);

    // fused QKV projection -> fp16 outputs
    hgemm_nt<<<dim3(NQKV / 128, M_TOT / 128), 256>>>(
        a2, w3, qhp, khp, vfp, M_TOT, HID_, 1);

    // in-place fp16 RoPE (q prescaled by 1/sqrt(HD)*log2(e))
    const float QSC = 0.08838834764831845f * 1.4426950408889634f;
    rope16_kernel<<<(ROPE_TOTAL + 255) / 256, 256>>>(qhp, khp, pos, QSC);
    vt16_kernel<<<(B_ * NKV_ * (HD_ / 4) * S_ + 255) / 256, 256>>>(vfp, vthp);

    cudaFuncSetAttribute(flash_tc, cudaFuncAttributeMaxDynamicSharedMemorySize,
                         FLASH_SMEM_BYTES);
    flash_tc<<<dim3(S_ / 128, NH_, B_), 256, FLASH_SMEM_BYTES>>>(qhp, khp, vthp, o2);

    // output projection -> fp32 out
    hgemm_nt<<<dim3(HID_ / 128, M_TOT / 128), 256>>>(
        o2, wo2, out, out, out, M_TOT, HID_, 0);
}